// round 11
// baseline (speedup 1.0000x reference)
#include <cuda_runtime.h>

// CombPool2d: out = (w_avg^2)*avg_pool2x2(x) + (w_max^2)*max_pool2x2(x)
// x: (16,192,224,224) fp32, out: (16,192,112,112) fp32. Pure HBM stream.
// sm_103a 256-bit loads: thread = 4x8 input patch -> 2x4 output block.
// Four lane-contiguous LDG.256 (ld.global.cs.v8.f32), two STG.128 stores.
// 1024B per warp per load instruction, fully dense. Exact grid, no guard.

#define B   16
#define C   192
#define HI  224
#define WI  224
#define HO  112
#define WO  112
#define H2  (HO / 2)   // output row-pairs = 56
#define WQ  (WO / 4)   // output col-quads = 28

struct alignas(32) f8 { float v[8]; };

__device__ __forceinline__ f8 ldg256_cs(const float* p)
{
    f8 r;
    asm volatile("ld.global.cs.v8.f32 {%0,%1,%2,%3,%4,%5,%6,%7}, [%8];"
                 : "=f"(r.v[0]), "=f"(r.v[1]), "=f"(r.v[2]), "=f"(r.v[3]),
                   "=f"(r.v[4]), "=f"(r.v[5]), "=f"(r.v[6]), "=f"(r.v[7])
                 : "l"(p));
    return r;
}

__global__ __launch_bounds__(256)
void comb_pool2d_kernel(const float* __restrict__ x,
                        const float* __restrict__ w_avg,
                        const float* __restrict__ w_max,
                        float* __restrict__ out)
{
    int tid = blockIdx.x * 256 + threadIdx.x;   // exact: no guard needed

    int wq = tid % WQ;          // output col-quad (4 output cols)
    int t  = tid / WQ;
    int h2 = t % H2;            // output row-pair (2 output rows)
    int bc = t / H2;            // fused batch*channel
    int c  = bc % C;

    // Input: rows 4*h2 .. 4*h2+3, cols 8*wq .. 8*wq+7 (4x8 patch, 32B/row)
    const float* xin = x + (size_t)bc * (HI * WI) + (size_t)(4 * h2) * WI + 8 * wq;

    // Four lane-contiguous 32B loads, front-batched (evict-first)
    f8 r0 = ldg256_cs(xin);
    f8 r1 = ldg256_cs(xin + WI);
    f8 r2 = ldg256_cs(xin + 2 * WI);
    f8 r3 = ldg256_cs(xin + 3 * WI);

    float wa = __ldg(w_avg + c);
    float wm = __ldg(w_max + c);
    float ca = wa * wa * 0.25f;   // folds the /4 of avg-pool
    float cm = wm * wm;

    float4 o0, o1;
    float* p0 = &o0.x;
    float* p1 = &o1.x;
#pragma unroll
    for (int j = 0; j < 4; j++) {
        float a0 = r0.v[2 * j], b0 = r0.v[2 * j + 1];
        float a1 = r1.v[2 * j], b1 = r1.v[2 * j + 1];
        float a2 = r2.v[2 * j], b2 = r2.v[2 * j + 1];
        float a3 = r3.v[2 * j], b3 = r3.v[2 * j + 1];
        // rows (0,1) -> output row 2*h2
        p0[j] = fmaf(ca, (a0 + b0) + (a1 + b1),
                     cm * fmaxf(fmaxf(a0, b0), fmaxf(a1, b1)));
        // rows (2,3) -> output row 2*h2+1
        p1[j] = fmaf(ca, (a2 + b2) + (a3 + b3),
                     cm * fmaxf(fmaxf(a2, b2), fmaxf(a3, b3)));
    }

    float* outp = out + (size_t)bc * (HO * WO) + (size_t)(2 * h2) * WO + 4 * wq;
    __stcs(reinterpret_cast<float4*>(outp),      o0);
    __stcs(reinterpret_cast<float4*>(outp + WO), o1);
}

extern "C" void kernel_launch(void* const* d_in, const int* in_sizes, int n_in,
                              void* d_out, int out_size)
{
    const float* x     = (const float*)d_in[0];
    const float* w_avg = (const float*)d_in[1];
    const float* w_max = (const float*)d_in[2];
    float* out = (float*)d_out;

    const int total  = B * C * H2 * WQ;          // 4,816,896
    const int blocks = total / 256;              // 18,816 exactly

    comb_pool2d_kernel<<<blocks, 256>>>(x, w_avg, w_max, out);
}